// round 4
// baseline (speedup 1.0000x reference)
#include <cuda_runtime.h>

// Depthwise 3x3 conv, stride 1, VALID, fp32.
// x: (16, 64, 512, 512), w: (64, 3, 3), out: (16, 64, 510, 510).
// Memory-bound: ~2.14 GB min traffic. Strategy: 4-wide x 102-tall strips per
// thread, 3-row register rotation (each input element loaded once), float4+
// float2 loads, float2 stores (row stride 2040 B is only 8B-aligned).

namespace {

constexpr int CH    = 64;
constexpr int H     = 512;
constexpr int W     = 512;
constexpr int OH    = 510;
constexpr int OW    = 510;
constexpr int CHUNK = 102;   // 5 chunks * 102 = 510, divisible by 3
constexpr int TPB   = 128;   // 128 threads * 4 outputs = 512 >= OW

__global__ __launch_bounds__(TPB)
void dwconv3x3_kernel(const float* __restrict__ x,
                      const float* __restrict__ wgt,
                      float* __restrict__ out)
{
    const int plane = blockIdx.x;              // n*CH + c
    const int c     = plane & (CH - 1);

    const float* __restrict__ in = x + (size_t)plane * (H * W);
    float* __restrict__ op       = out + (size_t)plane * (OH * OW);

    const float* wp = wgt + c * 9;
    const float w00 = __ldg(wp + 0), w01 = __ldg(wp + 1), w02 = __ldg(wp + 2);
    const float w10 = __ldg(wp + 3), w11 = __ldg(wp + 4), w12 = __ldg(wp + 5);
    const float w20 = __ldg(wp + 6), w21 = __ldg(wp + 7), w22 = __ldg(wp + 8);

    const int x0 = threadIdx.x * 4;            // 0, 4, ..., 508
    const int y0 = blockIdx.y * CHUNK;

    float r0[6], r1[6], r2[6];

    // Load 6 input columns [x0, x0+5] of row y into d. All addresses are
    // 16B-aligned (x0 multiple of 4 floats, row stride 2048 B).
    auto load_row = [&](float* d, int y) {
        const float4 a = *reinterpret_cast<const float4*>(in + y * W + x0);
        d[0] = a.x; d[1] = a.y; d[2] = a.z; d[3] = a.w;
        if (x0 + 4 < W) {
            const float2 b = *reinterpret_cast<const float2*>(in + y * W + x0 + 4);
            d[4] = b.x; d[5] = b.y;
        } else {
            d[4] = 0.f; d[5] = 0.f;            // x0 == 508: cols 512/513 unused
        }
    };

    // Compute output row y from input rows a (y), b (y+1), cc (y+2); store.
    auto proc = [&](const float* a, const float* b, const float* cc, int y) {
        float o[4];
        #pragma unroll
        for (int j = 0; j < 4; ++j) {
            float s;
            s = a[j]      * w00;
            s = fmaf(a[j + 1],  w01, s);
            s = fmaf(a[j + 2],  w02, s);
            s = fmaf(b[j],      w10, s);
            s = fmaf(b[j + 1],  w11, s);
            s = fmaf(b[j + 2],  w12, s);
            s = fmaf(cc[j],     w20, s);
            s = fmaf(cc[j + 1], w21, s);
            s = fmaf(cc[j + 2], w22, s);
            o[j] = s;
        }
        float* orow = op + (size_t)y * OW + x0;   // 8B-aligned always
        if (x0 + 4 <= OW) {
            reinterpret_cast<float2*>(orow)[0] = make_float2(o[0], o[1]);
            reinterpret_cast<float2*>(orow)[1] = make_float2(o[2], o[3]);
        } else {
            // x0 == 508: only outputs 508, 509 are valid
            reinterpret_cast<float2*>(orow)[0] = make_float2(o[0], o[1]);
        }
    };

    load_row(r0, y0);
    load_row(r1, y0 + 1);
    load_row(r2, y0 + 2);

    int y = y0;
    #pragma unroll 2
    for (int i = 0; i < CHUNK / 3; ++i) {
        // 3-stage rotation: zero register copies. Each stage computes one
        // output row and refills the now-oldest row buffer with row y+3.
        proc(r0, r1, r2, y);     load_row(r0, min(y + 3, H - 1));
        proc(r1, r2, r0, y + 1); load_row(r1, min(y + 4, H - 1));
        proc(r2, r0, r1, y + 2); load_row(r2, min(y + 5, H - 1));
        y += 3;
    }
}

} // namespace

extern "C" void kernel_launch(void* const* d_in, const int* in_sizes, int n_in,
                              void* d_out, int out_size)
{
    const float* x = (const float*)d_in[0];
    const float* w = (const float*)d_in[1];
    float* out     = (float*)d_out;

    const int planes = in_sizes[0] / (H * W);   // 16 * 64 = 1024
    dim3 grid(planes, OH / CHUNK);              // (1024, 5)
    dwconv3x3_kernel<<<grid, TPB>>>(x, w, out);
}

// round 5
// speedup vs baseline: 1.0274x; 1.0274x over previous
#include <cuda_runtime.h>

// Depthwise 3x3 conv, stride 1, VALID, fp32.
// x: (16, 64, 512, 512), w: (64, 3, 3), out: (16, 64, 510, 510).
//
// R4: minimal DRAM traffic (2.13 GB) but only 66.5% of peak BW — latency-bound
// (load->use distance of 1 stage => ~2 loads in flight per warp).
// R5: 6-row register ring. Load issued at stage k feeds the proc 4 stages
// later => ~8 loads in flight per warp; trades occupancy for MLP.

namespace {

constexpr int CH    = 64;
constexpr int H     = 512;
constexpr int W     = 512;
constexpr int OH    = 510;
constexpr int OW    = 510;
constexpr int CHUNK = 102;   // 5 chunks * 102 = 510; 102 = 17 * 6
constexpr int TPB   = 128;   // 128 threads * 4 outputs = 512 >= OW

__global__ __launch_bounds__(TPB)
void dwconv3x3_kernel(const float* __restrict__ x,
                      const float* __restrict__ wgt,
                      float* __restrict__ out)
{
    const int plane = blockIdx.x;              // n*CH + c
    const int c     = plane & (CH - 1);

    const float* __restrict__ in = x + (size_t)plane * (H * W);
    float* __restrict__ op       = out + (size_t)plane * (OH * OW);

    const float* wp = wgt + c * 9;
    const float w00 = __ldg(wp + 0), w01 = __ldg(wp + 1), w02 = __ldg(wp + 2);
    const float w10 = __ldg(wp + 3), w11 = __ldg(wp + 4), w12 = __ldg(wp + 5);
    const float w20 = __ldg(wp + 6), w21 = __ldg(wp + 7), w22 = __ldg(wp + 8);

    const int x0 = threadIdx.x * 4;            // 0, 4, ..., 508
    const int y0 = blockIdx.y * CHUNK;

    // 6-row ring of 6-column strips. All indices are compile-time constants
    // after full unroll, so everything stays in registers (~36 floats).
    float r[6][6];

    // Load 6 input columns [x0, x0+5] of row y. float4 is 16B-aligned
    // (x0 % 4 == 0, row stride 2048 B); the float2 halo overlaps the
    // neighbor thread's float4 (L1-absorbed).
    auto load_row = [&](float* d, int y) {
        const float4 a = *reinterpret_cast<const float4*>(in + y * W + x0);
        d[0] = a.x; d[1] = a.y; d[2] = a.z; d[3] = a.w;
        if (x0 + 4 < W) {
            const float2 b = *reinterpret_cast<const float2*>(in + y * W + x0 + 4);
            d[4] = b.x; d[5] = b.y;
        } else {
            d[4] = 0.f; d[5] = 0.f;            // x0 == 508: cols 512/513 unused
        }
    };

    // Output row y from input rows a (y), b (y+1), cc (y+2); float2 stores
    // (output row stride 2040 B is only 8B-aligned).
    auto proc = [&](const float* a, const float* b, const float* cc, int y) {
        float o[4];
        #pragma unroll
        for (int j = 0; j < 4; ++j) {
            float s;
            s = a[j]      * w00;
            s = fmaf(a[j + 1],  w01, s);
            s = fmaf(a[j + 2],  w02, s);
            s = fmaf(b[j],      w10, s);
            s = fmaf(b[j + 1],  w11, s);
            s = fmaf(b[j + 2],  w12, s);
            s = fmaf(cc[j],     w20, s);
            s = fmaf(cc[j + 1], w21, s);
            s = fmaf(cc[j + 2], w22, s);
            o[j] = s;
        }
        float* orow = op + (size_t)y * OW + x0;
        reinterpret_cast<float2*>(orow)[0] = make_float2(o[0], o[1]);
        if (x0 + 4 <= OW)                       // x0 == 508: outputs 510/511 invalid
            reinterpret_cast<float2*>(orow)[1] = make_float2(o[2], o[3]);
    };

    // Prologue: fill the ring with rows y0 .. y0+5 (max 413+5 < 512, in bounds).
    #pragma unroll
    for (int k = 0; k < 6; ++k)
        load_row(r[k], y0 + k);

    int y = y0;
    for (int i = 0; i < CHUNK / 6; ++i) {
        // Stage k: compute output y+k from ring slots (k, k+1, k+2) mod 6,
        // then refill slot k with row y+k+6 (consumed 4 stages later).
        proc(r[0], r[1], r[2], y + 0); load_row(r[0], min(y + 6,  H - 1));
        proc(r[1], r[2], r[3], y + 1); load_row(r[1], min(y + 7,  H - 1));
        proc(r[2], r[3], r[4], y + 2); load_row(r[2], min(y + 8,  H - 1));
        proc(r[3], r[4], r[5], y + 3); load_row(r[3], min(y + 9,  H - 1));
        proc(r[4], r[5], r[0], y + 4); load_row(r[4], min(y + 10, H - 1));
        proc(r[5], r[0], r[1], y + 5); load_row(r[5], min(y + 11, H - 1));
        y += 6;
    }
}

} // namespace

extern "C" void kernel_launch(void* const* d_in, const int* in_sizes, int n_in,
                              void* d_out, int out_size)
{
    const float* x = (const float*)d_in[0];
    const float* w = (const float*)d_in[1];
    float* out     = (float*)d_out;

    const int planes = in_sizes[0] / (H * W);   // 16 * 64 = 1024
    dim3 grid(planes, OH / CHUNK);              // (1024, 5)
    dwconv3x3_kernel<<<grid, TPB>>>(x, w, out);
}

// round 6
// speedup vs baseline: 1.1683x; 1.1372x over previous
#include <cuda_runtime.h>

// Depthwise 3x3 conv, stride 1, VALID, fp32.
// x: (16, 64, 512, 512), w: (64, 3, 3), out: (16, 64, 510, 510).
//
// R5: 6-row register ring, DRAM 73%, but grid=5120 -> 3.46 waves (13.5%
// quantization loss) and 6 wasted clamped loads per chunk.
// R6: CHUNK=30 (grid 17408 -> 11.76 waves, ~2% quantization) + peeled
// epilogue so each block reads exactly CHUNK+2 rows, no clamps.

namespace {

constexpr int CH    = 64;
constexpr int H     = 512;
constexpr int W     = 512;
constexpr int OH    = 510;
constexpr int OW    = 510;
constexpr int CHUNK = 30;    // 17 chunks * 30 = 510; multiple of 6
constexpr int TPB   = 128;   // 128 threads * 4 outputs = 512 >= OW

__global__ __launch_bounds__(TPB)
void dwconv3x3_kernel(const float* __restrict__ x,
                      const float* __restrict__ wgt,
                      float* __restrict__ out)
{
    const int plane = blockIdx.x;              // n*CH + c
    const int c     = plane & (CH - 1);

    const float* __restrict__ in = x + (size_t)plane * (H * W);
    float* __restrict__ op       = out + (size_t)plane * (OH * OW);

    const float* wp = wgt + c * 9;
    const float w00 = __ldg(wp + 0), w01 = __ldg(wp + 1), w02 = __ldg(wp + 2);
    const float w10 = __ldg(wp + 3), w11 = __ldg(wp + 4), w12 = __ldg(wp + 5);
    const float w20 = __ldg(wp + 6), w21 = __ldg(wp + 7), w22 = __ldg(wp + 8);

    const int x0 = threadIdx.x * 4;            // 0, 4, ..., 508
    const int y0 = blockIdx.y * CHUNK;         // 0, 30, ..., 480

    // 6-row ring of 6-column strips; fully unrolled -> all registers.
    float r[6][6];

    // Load input columns [x0, x0+5] of row y. float4 16B-aligned; float2
    // halo overlaps the neighbor thread's float4 (L1-absorbed).
    auto load_row = [&](float* d, int y) {
        const float4 a = *reinterpret_cast<const float4*>(in + y * W + x0);
        d[0] = a.x; d[1] = a.y; d[2] = a.z; d[3] = a.w;
        if (x0 + 4 < W) {
            const float2 b = *reinterpret_cast<const float2*>(in + y * W + x0 + 4);
            d[4] = b.x; d[5] = b.y;
        } else {
            d[4] = 0.f; d[5] = 0.f;            // x0 == 508: cols 512/513 unused
        }
    };

    // Output row y from input rows a (y), b (y+1), cc (y+2); float2 stores
    // (output row stride 2040 B is only 8B-aligned).
    auto proc = [&](const float* a, const float* b, const float* cc, int y) {
        float o[4];
        #pragma unroll
        for (int j = 0; j < 4; ++j) {
            float s;
            s = a[j]      * w00;
            s = fmaf(a[j + 1],  w01, s);
            s = fmaf(a[j + 2],  w02, s);
            s = fmaf(b[j],      w10, s);
            s = fmaf(b[j + 1],  w11, s);
            s = fmaf(b[j + 2],  w12, s);
            s = fmaf(cc[j],     w20, s);
            s = fmaf(cc[j + 1], w21, s);
            s = fmaf(cc[j + 2], w22, s);
            o[j] = s;
        }
        float* orow = op + (size_t)y * OW + x0;
        reinterpret_cast<float2*>(orow)[0] = make_float2(o[0], o[1]);
        if (x0 + 4 <= OW)                       // x0 == 508: outputs 510/511 invalid
            reinterpret_cast<float2*>(orow)[1] = make_float2(o[2], o[3]);
    };

    // Prologue: rows y0 .. y0+5 (y0 <= 480, so max row 485 — in bounds).
    #pragma unroll
    for (int k = 0; k < 6; ++k)
        load_row(r[k], y0 + k);

    int y = y0;
    // Main iterations: each computes 6 output rows and prefetches the next 6
    // input rows (load at stage k consumed 4 stages later).
    #pragma unroll 1
    for (int i = 0; i < CHUNK / 6 - 1; ++i) {
        proc(r[0], r[1], r[2], y + 0); load_row(r[0], y + 6);
        proc(r[1], r[2], r[3], y + 1); load_row(r[1], y + 7);
        proc(r[2], r[3], r[4], y + 2); load_row(r[2], y + 8);
        proc(r[3], r[4], r[5], y + 3); load_row(r[3], y + 9);
        proc(r[4], r[5], r[0], y + 4); load_row(r[4], y + 10);
        proc(r[5], r[0], r[1], y + 5); load_row(r[5], y + 11);
        y += 6;
    }

    // Epilogue: only rows y+6, y+7 are still needed (consumed at stages 4/5).
    // y+7 = y0+31 <= 511 for the last chunk — exactly in bounds, no clamps.
    proc(r[0], r[1], r[2], y + 0); load_row(r[0], y + 6);
    proc(r[1], r[2], r[3], y + 1); load_row(r[1], y + 7);
    proc(r[2], r[3], r[4], y + 2);
    proc(r[3], r[4], r[5], y + 3);
    proc(r[4], r[5], r[0], y + 4);
    proc(r[5], r[0], r[1], y + 5);
}

} // namespace

extern "C" void kernel_launch(void* const* d_in, const int* in_sizes, int n_in,
                              void* d_out, int out_size)
{
    const float* x = (const float*)d_in[0];
    const float* w = (const float*)d_in[1];
    float* out     = (float*)d_out;

    const int planes = in_sizes[0] / (H * W);   // 16 * 64 = 1024
    dim3 grid(planes, OH / CHUNK);              // (1024, 17)
    dwconv3x3_kernel<<<grid, TPB>>>(x, w, out);
}

// round 7
// speedup vs baseline: 1.1781x; 1.0083x over previous
#include <cuda_runtime.h>

// Depthwise 3x3 conv, stride 1, VALID, fp32.
// x: (16, 64, 512, 512), w: (64, 3, 3), out: (16, 64, 510, 510).
//
// R6: CHUNK=30 ring, DRAM 79.9%, 332.8 us. Remaining losses are distributed:
// R7: (a) grid swap (chunk fastest) so vertically-adjacent chunks of the same
//     plane run concurrently -> 2 halo rows/chunk hit L2 (-3% DRAM reads);
//     (b) __stcs streaming stores (evict-first) so outputs don't evict the
//     halo lines from L2;
//     (c) shuffle-halo: d[4],d[5] come from neighbor lane's float4 via
//     __shfl_down_sync (lane 31 keeps its float2 load) -> ~half the LDGs;
//     (d) even output rows (offset 2040*y, 16B-aligned) use one STG.128.

namespace {

constexpr int CH    = 64;
constexpr int H     = 512;
constexpr int W     = 512;
constexpr int OH    = 510;
constexpr int OW    = 510;
constexpr int CHUNK = 30;    // 17 chunks * 30 = 510; multiple of 6
constexpr int TPB   = 128;   // 128 threads * 4 outputs = 512 >= OW

__global__ __launch_bounds__(TPB)
void dwconv3x3_kernel(const float* __restrict__ x,
                      const float* __restrict__ wgt,
                      float* __restrict__ out)
{
    const int plane = blockIdx.y;              // n*CH + c   (slow axis)
    const int c     = plane & (CH - 1);
    const int y0    = blockIdx.x * CHUNK;      // chunk = fast axis -> adjacent
                                               // chunks of a plane co-resident
    const float* __restrict__ in = x + (size_t)plane * (H * W);
    float* __restrict__ op       = out + (size_t)plane * (OH * OW);

    const float* wp = wgt + c * 9;
    const float w00 = __ldg(wp + 0), w01 = __ldg(wp + 1), w02 = __ldg(wp + 2);
    const float w10 = __ldg(wp + 3), w11 = __ldg(wp + 4), w12 = __ldg(wp + 5);
    const float w20 = __ldg(wp + 6), w21 = __ldg(wp + 7), w22 = __ldg(wp + 8);

    const int x0   = threadIdx.x * 4;          // 0, 4, ..., 508
    const int lane = threadIdx.x & 31;

    // 6-row ring of 6-column strips; fully unrolled -> all registers.
    float r[6][6];

    // One float4 per row per thread; halo cols 4,5 shuffled from lane+1
    // (that lane's a.x, a.y). Lane 31 loads its own float2 halo.
    auto load_row = [&](float* d, int y) {
        const float4 a = *reinterpret_cast<const float4*>(in + y * W + x0);
        d[0] = a.x; d[1] = a.y; d[2] = a.z; d[3] = a.w;
        d[4] = __shfl_down_sync(0xffffffffu, a.x, 1);
        d[5] = __shfl_down_sync(0xffffffffu, a.y, 1);
        if (lane == 31) {
            if (x0 + 4 < W) {
                const float2 b = *reinterpret_cast<const float2*>(in + y * W + x0 + 4);
                d[4] = b.x; d[5] = b.y;
            } else {
                d[4] = 0.f; d[5] = 0.f;        // x0 == 508: cols 512/513 unused
            }
        }
    };

    // Output row y from rows a (y), b (y+1), cc (y+2). AL16: row byte offset
    // 2040*y is 16B-aligned iff y even; stage parity == row parity (y0 even).
    // Streaming stores keep L2 for input halo reuse.
    auto proc = [&](const float* a, const float* b, const float* cc, int y,
                    bool al16) {
        float o[4];
        #pragma unroll
        for (int j = 0; j < 4; ++j) {
            float s;
            s = a[j]      * w00;
            s = fmaf(a[j + 1],  w01, s);
            s = fmaf(a[j + 2],  w02, s);
            s = fmaf(b[j],      w10, s);
            s = fmaf(b[j + 1],  w11, s);
            s = fmaf(b[j + 2],  w12, s);
            s = fmaf(cc[j],     w20, s);
            s = fmaf(cc[j + 1], w21, s);
            s = fmaf(cc[j + 2], w22, s);
            o[j] = s;
        }
        float* orow = op + (size_t)y * OW + x0;
        if (x0 + 4 <= OW) {
            if (al16) {
                __stcs(reinterpret_cast<float4*>(orow),
                       make_float4(o[0], o[1], o[2], o[3]));
            } else {
                __stcs(reinterpret_cast<float2*>(orow),     make_float2(o[0], o[1]));
                __stcs(reinterpret_cast<float2*>(orow) + 1, make_float2(o[2], o[3]));
            }
        } else {                                // x0 == 508: only 508/509 valid
            __stcs(reinterpret_cast<float2*>(orow), make_float2(o[0], o[1]));
        }
    };

    // Prologue: rows y0 .. y0+5 (y0 <= 480 -> max row 485, in bounds).
    #pragma unroll
    for (int k = 0; k < 6; ++k)
        load_row(r[k], y0 + k);

    int y = y0;
    // Each iter: 6 output rows + prefetch of the next 6 input rows
    // (load at stage k consumed 4 stages later).
    #pragma unroll 1
    for (int i = 0; i < CHUNK / 6 - 1; ++i) {
        proc(r[0], r[1], r[2], y + 0, true ); load_row(r[0], y + 6);
        proc(r[1], r[2], r[3], y + 1, false); load_row(r[1], y + 7);
        proc(r[2], r[3], r[4], y + 2, true ); load_row(r[2], y + 8);
        proc(r[3], r[4], r[5], y + 3, false); load_row(r[3], y + 9);
        proc(r[4], r[5], r[0], y + 4, true ); load_row(r[4], y + 10);
        proc(r[5], r[0], r[1], y + 5, false); load_row(r[5], y + 11);
        y += 6;
    }

    // Epilogue: only rows y+6, y+7 still needed (stages 4/5).
    // y+7 = y0+31 <= 511 for the last chunk — in bounds, no clamps.
    proc(r[0], r[1], r[2], y + 0, true ); load_row(r[0], y + 6);
    proc(r[1], r[2], r[3], y + 1, false); load_row(r[1], y + 7);
    proc(r[2], r[3], r[4], y + 2, true );
    proc(r[3], r[4], r[5], y + 3, false);
    proc(r[4], r[5], r[0], y + 4, true );
    proc(r[5], r[0], r[1], y + 5, false);
}

} // namespace

extern "C" void kernel_launch(void* const* d_in, const int* in_sizes, int n_in,
                              void* d_out, int out_size)
{
    const float* x = (const float*)d_in[0];
    const float* w = (const float*)d_in[1];
    float* out     = (float*)d_out;

    const int planes = in_sizes[0] / (H * W);   // 16 * 64 = 1024
    dim3 grid(OH / CHUNK, planes);              // (17, 1024) — chunk fastest
    dwconv3x3_kernel<<<grid, TPB>>>(x, w, out);
}